// round 15
// baseline (speedup 1.0000x reference)
#include <cuda_runtime.h>

#define BB 8
#define NN 2000
#define CC 81
#define MAXI 100
#define HH 512
#define WW 512
#define MSEL 256
#define GRID 128

// scratch (device globals: no allocation allowed)
__device__ float4 g_box4[BB * NN];
__device__ unsigned long long g_key[BB * 2048];   // 16 sorted runs of 128 per batch
__device__ unsigned g_M[BB * 256 * 8];            // suppression matrix per batch
__device__ unsigned g_bar[4];  // [0]=main [1]=matrix [2]=det (monotone)

struct SM {
    unsigned long long K[2048];                                   // 16KB
    float sy1[MSEL], sx1[MSEL], sy2[MSEL], sx2[MSEL], ssc[MSEL];  // 5KB
    int scl[MSEL];                                                // 1KB
    float ky1[MAXI], kx1[MAXI], ky2[MAXI], kx2[MAXI], kar[MAXI];  // 2KB
    int nvalid, s_kc, s_fb;
    int round;
};
struct P3S {
    int hs[MAXI], he[MAXI];
    unsigned wp[MAXI];          // ws | (we<<16), exact integer x-range
    unsigned ranges[32][MAXI];  // per-row compacted interval list
    int nact[32];
    unsigned words[32][16];     // 512-bit coverage per row
};

__device__ __forceinline__ void cswap(unsigned long long& v, int i, int j, int k) {
    unsigned long long pv = __shfl_xor_sync(0xffffffffu, v, j);
    bool take_max = (((i & k) == 0) ^ ((i & j) != 0));
    bool pick = take_max ? (pv > v) : (pv < v);
    if (pick) v = pv;
}

// exact: min p in [0,512] with (p+0.5f)*(1/512) >= a  (float preds == reference)
__device__ __forceinline__ int pmin_ge(float a) {
    const float inv = 1.0f / 512.0f;
    int p = (int)(512.0f * a);
    p = min(max(p, 0), 512);
    while (p > 0 && ((float)(p - 1) + 0.5f) * inv >= a) --p;
    while (p < 512 && !(((float)p + 0.5f) * inv >= a)) ++p;
    return p;
}

// key layout: [63:32]=score bits, [31:0] = ((2047-n)<<7) | cls
// descending sort => score desc, tie -> smaller n first (same as reference).
__device__ __forceinline__ int key_n(unsigned long long key) {
    return 2047 - (int)(((unsigned)(key & 0xFFFFFFFFull)) >> 7);
}
__device__ __forceinline__ int key_cls(unsigned long long key) {
    return (int)((unsigned)(key & 0x7Fu));
}

__global__ void __launch_bounds__(1024, 1)
fused_all(const float* __restrict__ rois,
          const float* __restrict__ probs,
          const float* __restrict__ deltas,
          const float* __restrict__ stdv,
          float* __restrict__ det,
          float* __restrict__ mask) {
    __shared__ __align__(16) char smraw[sizeof(SM)];
    SM& S = *(SM*)smraw;
    int tid = threadIdx.x;
    int lane = tid & 31;
    int wrp = tid >> 5;
    int bid = blockIdx.x;

    // hoisted bbox_std_dev (uniform, cached)
    float sd0 = stdv[0], sd1 = stdv[1], sd2 = stdv[2], sd3 = stdv[3];

    // ============ Phase 1: refine + slice sort (128 blocks, slice=128) ============
    {
        int b = bid >> 4, s = bid & 15;
        int n0 = s * 128 + wrp * 4;  // warp's 4 proposals
        if (n0 < NN) {
            unsigned mq[4];
            unsigned cq[4];
#pragma unroll
            for (int q = 0; q < 4; ++q) {
                const float* p = probs + (long long)(b * NN + n0 + q) * CC;
                float b0 = p[lane];
                float b1 = p[lane + 32];
                float b2 = (lane + 64 < CC) ? p[lane + 64] : -1.0f;
                int c = lane;
                float bst = b0;
                if (b1 > bst) { bst = b1; c = lane + 32; }
                if (b2 > bst) { bst = b2; c = lane + 64; }
                // REDUX argmax: max score bits (positive floats, bit-monotone),
                // then min class among tied lanes -> first max (== jnp.argmax)
                unsigned sb = __float_as_uint(bst);
                unsigned m = __reduce_max_sync(0xffffffffu, sb);
                unsigned cm = __reduce_min_sync(0xffffffffu, (sb == m) ? (unsigned)c : 0xFFFFu);
                mq[q] = m;
                cq[q] = cm;
            }
            if (lane < 4) {
                int n = n0 + lane;
                int gw = b * NN + n;
                float bst = __uint_as_float(mq[lane]);
                int c = (int)cq[lane];

                float4 dd = *(const float4*)(deltas + ((long long)gw * CC + c) * 4);
                float dy = dd.x * sd0;
                float dx = dd.y * sd1;
                float dh = dd.z * sd2;
                float dw = dd.w * sd3;
                float4 rr = *(const float4*)(rois + gw * 4);
                float y1 = rr.x, x1 = rr.y, y2 = rr.z, x2 = rr.w;
                float h = y2 - y1, w2 = x2 - x1;
                float cy = y1 + 0.5f * h + dy * h;
                float cx = x1 + 0.5f * w2 + dx * w2;
                h = h * expf(dh);
                w2 = w2 * expf(dw);
                float4 nb;
                nb.x = fminf(fmaxf(cy - 0.5f * h, 0.0f), 1.0f);
                nb.y = fminf(fmaxf(cx - 0.5f * w2, 0.0f), 1.0f);
                nb.z = fminf(fmaxf(cy + 0.5f * h, 0.0f), 1.0f);
                nb.w = fminf(fmaxf(cx + 0.5f * w2, 0.0f), 1.0f);
                g_box4[gw] = nb;
                bool valid = (c > 0) && (bst >= 0.05f);
                S.K[wrp * 4 + lane] =
                    valid ? ((((unsigned long long)mq[lane]) << 32) |
                             (((unsigned long long)(unsigned)(2047 - n)) << 7) |
                             (unsigned long long)(unsigned)c)
                          : 0ull;
            }
        } else {
            if (lane < 4) S.K[wrp * 4 + lane] = 0ull;
        }
        __syncthreads();

        // sort the 128 slice keys descending (2 warps, registers + 2 smem passes)
        if (tid < 64) {
            int w2 = tid >> 5, l = tid & 31;
            int i0 = w2 * 64 + l, i1 = i0 + 32;
            unsigned long long r0 = S.K[i0], r1 = S.K[i1];
#pragma unroll
            for (int k = 2; k <= 32; k <<= 1)
#pragma unroll
                for (int j = k >> 1; j > 0; j >>= 1) { cswap(r0, i0, j, k); cswap(r1, i1, j, k); }
            {   // k=64: j=32 is r0<->r1; direction alternates by group
                bool desc = ((w2 & 1) == 0);
                if (desc ? (r0 < r1) : (r0 > r1)) {
                    unsigned long long t = r0; r0 = r1; r1 = t;
                }
#pragma unroll
                for (int j = 16; j > 0; j >>= 1) { cswap(r0, i0, j, 64); cswap(r1, i1, j, 64); }
            }
            S.K[i0] = r0;
            S.K[i1] = r1;
        }
        __syncthreads();
        if (tid < 64) {  // k=128, j=64 (desc everywhere)
            unsigned long long a = S.K[tid], c = S.K[tid + 64];
            if (a < c) { S.K[tid] = c; S.K[tid + 64] = a; }
        }
        __syncthreads();
        if (tid < 64) {  // k=128, j=32
            int i = (tid >> 5) * 64 + (tid & 31);
            unsigned long long a = S.K[i], c = S.K[i + 32];
            if (a < c) { S.K[i] = c; S.K[i + 32] = a; }
        }
        __syncthreads();
        if (tid < 64) {  // k=128, j=16..1 + write run to global
            int w2 = tid >> 5, l = tid & 31;
            int i0 = w2 * 64 + l, i1 = i0 + 32;
            unsigned long long r0 = S.K[i0], r1 = S.K[i1];
#pragma unroll
            for (int j = 16; j > 0; j >>= 1) { cswap(r0, i0, j, 128); cswap(r1, i1, j, 128); }
            g_key[(bid >> 4) * 2048 + (bid & 15) * 128 + i0] = r0;
            g_key[(bid >> 4) * 2048 + (bid & 15) * 128 + i1] = r1;
        }
    }

    // ---- main grid barrier; every block learns its replay round ----
    __threadfence();
    __syncthreads();
    if (tid == 0) {
        unsigned t = atomicAdd(&g_bar[0], 1u);
        unsigned round = t / GRID;
        S.round = (int)round;
        unsigned target = (round + 1u) * GRID;
        while (*(volatile unsigned*)&g_bar[0] < target) {}
    }
    __syncthreads();
    unsigned round = (unsigned)S.round;

    // ============ Phase 2B/2C: merge -> top-256; matrix slice (blocks 0..63) ============
    if (bid < 64) {
        int b = bid >> 3, s2 = bid & 7;
        if (tid == 0) S.nvalid = 0;
        __syncthreads();
        unsigned long long k0 = g_key[b * 2048 + tid];
        unsigned long long k1 = g_key[b * 2048 + 1024 + tid];
        S.K[tid] = k0;
        S.K[1024 + tid] = k1;
        unsigned m0 = __ballot_sync(0xffffffffu, k0 != 0ull);
        unsigned m1 = __ballot_sync(0xffffffffu, k1 != 0ull);
        if (lane == 0) atomicAdd(&S.nvalid, __popc(m0) + __popc(m1));
        __syncthreads();

        // Round 1: 16 runs(128) -> 8 runs(256), FULL merge
        {
            int g = tid >> 7, i = tid & 127, base = g * 256;
            unsigned long long a = S.K[base + i], c = S.K[base + 255 - i];
            unsigned long long hi = a > c ? a : c, lo = a > c ? c : a;
            __syncthreads();
            S.K[base + i] = hi;
            S.K[base + 128 + i] = lo;
        }
        __syncthreads();
        for (int j = 64; j > 0; j >>= 1) {
            int seg = tid >> 7, cid = tid & 127;
            int i2 = ((cid & ~(j - 1)) << 1) | (cid & (j - 1));
            int a1 = seg * 256 + i2;
            unsigned long long x = S.K[a1], y = S.K[a1 + j];
            if (x < y) { S.K[a1] = y; S.K[a1 + j] = x; }
            __syncthreads();
        }
        // Round 2: 8 -> 4 (top-256 kept)
        {
            int g = tid >> 8, i = tid & 255;
            unsigned long long a = S.K[(2 * g) * 256 + i];
            unsigned long long c = S.K[(2 * g + 1) * 256 + 255 - i];
            unsigned long long L = a > c ? a : c;
            __syncthreads();
            S.K[g * 256 + i] = L;
        }
        __syncthreads();
        for (int j = 128; j > 0; j >>= 1) {
            if (tid < 512) {
                int seg = tid >> 7, cid = tid & 127;
                int i2 = ((cid & ~(j - 1)) << 1) | (cid & (j - 1));
                int a1 = seg * 256 + i2;
                unsigned long long x = S.K[a1], y = S.K[a1 + j];
                if (x < y) { S.K[a1] = y; S.K[a1 + j] = x; }
            }
            __syncthreads();
        }
        // Round 3: 4 -> 2
        {
            unsigned long long L = 0;
            int g = tid >> 8, i = tid & 255;
            if (tid < 512) {
                unsigned long long a = S.K[(2 * g) * 256 + i];
                unsigned long long c = S.K[(2 * g + 1) * 256 + 255 - i];
                L = a > c ? a : c;
            }
            __syncthreads();
            if (tid < 512) S.K[g * 256 + i] = L;
        }
        __syncthreads();
        for (int j = 128; j > 0; j >>= 1) {
            if (tid < 256) {
                int seg = tid >> 7, cid = tid & 127;
                int i2 = ((cid & ~(j - 1)) << 1) | (cid & (j - 1));
                int a1 = seg * 256 + i2;
                unsigned long long x = S.K[a1], y = S.K[a1 + j];
                if (x < y) { S.K[a1] = y; S.K[a1 + j] = x; }
            }
            __syncthreads();
        }
        // Round 4: 2 -> 1 (final top-256 descending in K[0..256))
        {
            unsigned long long L = 0;
            if (tid < 256) {
                unsigned long long a = S.K[tid];
                unsigned long long c = S.K[511 - tid];
                L = a > c ? a : c;
            }
            __syncthreads();
            if (tid < 256) S.K[tid] = L;
        }
        __syncthreads();
        for (int j = 128; j > 0; j >>= 1) {
            if (tid < 128) {
                int cid = tid;
                int i2 = ((cid & ~(j - 1)) << 1) | (cid & (j - 1));
                unsigned long long x = S.K[i2], y = S.K[i2 + j];
                if (x < y) { S.K[i2] = y; S.K[i2 + j] = x; }
            }
            __syncthreads();
        }

        // gather selected candidate boxes (cls decoded from key; no g_cls load)
        if (tid < MSEL) {
            unsigned long long key = S.K[tid];
            unsigned sb = (unsigned)(key >> 32);
            if (sb) {
                int idx = key_n(key);
                int gi = b * NN + idx;
                float4 bx = g_box4[gi];
                S.sy1[tid] = bx.x; S.sx1[tid] = bx.y; S.sy2[tid] = bx.z; S.sx2[tid] = bx.w;
                S.scl[tid] = key_cls(key);
                S.ssc[tid] = __uint_as_float(sb);
            } else {
                S.sy1[tid] = 0.f; S.sx1[tid] = 0.f; S.sy2[tid] = 0.f; S.sx2[tid] = 0.f;
                S.scl[tid] = 0;
                S.ssc[tid] = -1.0f;
            }
        }
        __syncthreads();

        // matrix slice: warp -> row r = s2*32 + wrp, all 8 column-words
        {
            int r = s2 * 32 + wrp;
            float cfr = (float)S.scl[r];
            float ry1 = S.sy1[r] + 2.0f * cfr;
            float rx1 = S.sx1[r] + 2.0f * cfr;
            float ry2 = S.sy2[r] + 2.0f * cfr;
            float rx2 = S.sx2[r] + 2.0f * cfr;
            float rar = (ry2 - ry1) * (rx2 - rx1);
#pragma unroll
            for (int t = 0; t < 8; ++t) {
                int j = t * 32 + lane;
                float cfj = (float)S.scl[j];
                float jy1 = S.sy1[j] + 2.0f * cfj;
                float jx1 = S.sx1[j] + 2.0f * cfj;
                float jy2 = S.sy2[j] + 2.0f * cfj;
                float jx2 = S.sx2[j] + 2.0f * cfj;
                float jar = (jy2 - jy1) * (jx2 - jx1);
                float yy1 = fmaxf(ry1, jy1);
                float xx1 = fmaxf(rx1, jx1);
                float yy2 = fminf(ry2, jy2);
                float xx2 = fminf(rx2, jx2);
                float inter = fmaxf(yy2 - yy1, 0.0f) * fmaxf(xx2 - xx1, 0.0f);
                float uni = rar + jar - inter;
                float iou = inter / fmaxf(uni, 1e-12f);
                unsigned bal = __ballot_sync(0xffffffffu, iou > 0.3f);
                if (lane == 0) g_M[(b * 256 + r) * 8 + t] = bal;
            }
        }
        __threadfence();
        __syncthreads();
        if (tid == 0) atomicAdd(&g_bar[1], 1u);  // matrix slice ready
    }

    // ============ Phase 2D: greedy NMS (8 blocks; sel still in smem) ============
    if (bid < 64 && (bid & 7) == 0) {
        int b = bid >> 3;
        if (tid == 0) {
            unsigned target = (round + 1u) * 64u;
            while (*(volatile unsigned*)&g_bar[1] < target) {}
        }
        __syncthreads();

        // preload this batch's matrix into shared (S.K region is dead)
        unsigned* Msm = (unsigned*)S.K;
        for (int i = tid; i < 2048; i += 1024) Msm[i] = __ldcg(&g_M[b * 2048 + i]);
        __syncthreads();

        if (wrp == 0) {
            unsigned rem[8] = {0, 0, 0, 0, 0, 0, 0, 0};
            int kc = 0;
            bool done = false;
            unsigned lower = (1u << lane) - 1u;
            for (int c = 0; c < 8 && !done; ++c) {
                int i = c * 32 + lane;
                unsigned row[8];
#pragma unroll
                for (int w = 0; w < 8; ++w) row[w] = Msm[i * 8 + w];
                bool v = S.ssc[i] > 0.0f;
                bool psup = (rem[c] >> lane) & 1u;
                unsigned wchunk = row[c] & lower;

                bool k = v && !psup;
                unsigned km = __ballot_sync(0xffffffffu, k);
                for (int it = 0; it < 40; ++it) {
                    bool kn = v && !psup && ((wchunk & km) == 0u);
                    unsigned km2 = __ballot_sync(0xffffffffu, kn);
                    if (km2 == km) break;
                    km = km2;
                }
                k = (km >> lane) & 1u;

                if (km) {
                    int cnt = __popc(km);
                    int need = MAXI - kc;
                    int pos = __popc(km & lower);
                    if (k && pos < need) {
                        float* dr = det + (b * MAXI + kc + pos) * 6;
                        dr[0] = S.sy1[i]; dr[1] = S.sx1[i]; dr[2] = S.sy2[i]; dr[3] = S.sx2[i];
                        dr[4] = (float)S.scl[i]; dr[5] = S.ssc[i];
                    }
                    if (cnt >= need) {
                        kc = MAXI;
                        done = true;
                    } else {
#pragma unroll
                        for (int w = 0; w < 8; ++w)
                            rem[w] |= __reduce_or_sync(0xffffffffu, k ? row[w] : 0u);
                        kc += cnt;
                    }
                }
            }
            if (lane == 0) {
                S.s_kc = kc;
                S.s_fb = (kc < MAXI && S.nvalid > MSEL) ? 1 : 0;
            }
        }
        __syncthreads();

        // rare fallback: serial warp NMS over virtual 16-way merged stream
        if (S.s_fb && wrp == 0) {
            int kc = 0;
            int hp[16];
#pragma unroll
            for (int r = 0; r < 16; ++r) hp[r] = 0;
            for (int iter = 0; iter < NN && kc < MAXI; ++iter) {
                unsigned long long bk = 0;
                int br = -1;
#pragma unroll
                for (int r = 0; r < 16; ++r) {
                    if (hp[r] < 128) {
                        unsigned long long kk = __ldg(&g_key[b * 2048 + r * 128 + hp[r]]);
                        if (kk > bk) { bk = kk; br = r; }
                    }
                }
                if (bk == 0) break;
                hp[br]++;
                int idx = key_n(bk);
                int gi = b * NN + idx;
                float4 bx = g_box4[gi];
                float y1 = bx.x, x1 = bx.y, y2 = bx.z, x2 = bx.w;
                float cf = (float)key_cls(bk);
                float score = __uint_as_float((unsigned)(bk >> 32));
                float oy1 = y1 + 2.0f * cf, ox1 = x1 + 2.0f * cf;
                float oy2 = y2 + 2.0f * cf, ox2 = x2 + 2.0f * cf;
                float ar = (oy2 - oy1) * (ox2 - ox1);
                bool sup = false;
                for (int j = lane; j < kc; j += 32) {
                    float yy1 = fmaxf(oy1, S.ky1[j]);
                    float xx1 = fmaxf(ox1, S.kx1[j]);
                    float yy2 = fminf(oy2, S.ky2[j]);
                    float xx2 = fminf(ox2, S.kx2[j]);
                    float inter = fmaxf(yy2 - yy1, 0.0f) * fmaxf(xx2 - xx1, 0.0f);
                    float uni = ar + S.kar[j] - inter;
                    float iou = inter / fmaxf(uni, 1e-12f);
                    sup |= (iou > 0.3f);
                }
                if (!__any_sync(0xffffffffu, sup)) {
                    if (lane == 0) {
                        S.ky1[kc] = oy1; S.kx1[kc] = ox1; S.ky2[kc] = oy2; S.kx2[kc] = ox2;
                        S.kar[kc] = ar;
                        float* dr = det + (b * MAXI + kc) * 6;
                        dr[0] = y1; dr[1] = x1; dr[2] = y2; dr[3] = x2;
                        dr[4] = cf; dr[5] = score;
                    }
                    kc++;
                }
                __syncwarp();
            }
            if (lane == 0) S.s_kc = kc;
        }
        __syncthreads();

        int kc = S.s_kc;
        for (int t = tid; t < (MAXI - kc) * 6; t += 1024)
            det[(b * MAXI + kc) * 6 + t] = 0.0f;
        __threadfence();
        __syncthreads();
        if (tid == 0) atomicAdd(&g_bar[2], 1u);  // det[b] ready
    }

    // ============ Phase 3: mask via exact integer intervals + bitmask ============
    if (tid == 0) {
        unsigned td = (round + 1u) * 8u;
        while (*(volatile unsigned*)&g_bar[2] < td) {}
    }
    __syncthreads();  // also fences smem reuse below

    {
        P3S& Q = *(P3S*)smraw;
        int b = bid >> 4;
        int h0 = (bid & 15) * 32;  // this block's 32 rows

        // load det rows, compute EXACT integer pixel ranges
        if (tid < MAXI) {
            const float* dr = det + (b * MAXI + tid) * 6;
            float2 p01 = __ldcg((const float2*)dr);
            float2 p23 = __ldcg((const float2*)(dr + 2));
            Q.hs[tid] = pmin_ge(p01.x);             // y1
            Q.he[tid] = pmin_ge(p23.x);             // y2 (exclusive)
            int ws = pmin_ge(p01.y);                // x1
            int we = pmin_ge(p23.y);                // x2 (exclusive)
            Q.wp[tid] = (unsigned)ws | ((unsigned)we << 16);
        }
        __syncthreads();

        // warp r: compact active intervals for row h0+r (ballot, no atomics)
        {
            int h = h0 + wrp;
            int cnt = 0;
#pragma unroll
            for (int q = 0; q < 4; ++q) {
                int j = q * 32 + lane;
                bool act = false;
                unsigned wpv = 0;
                if (j < MAXI) {
                    wpv = Q.wp[j];
                    int ws = (int)(wpv & 0xffffu), we = (int)(wpv >> 16);
                    act = (h >= Q.hs[j]) && (h < Q.he[j]) && (ws < we);
                }
                unsigned bal = __ballot_sync(0xffffffffu, act);
                int pos = cnt + __popc(bal & ((1u << lane) - 1u));
                if (act) Q.ranges[wrp][pos] = wpv;
                cnt += __popc(bal);
            }
            if (lane == 0) Q.nact[wrp] = cnt;
        }
        __syncthreads();

        // build 512-bit coverage words: thread -> (row, word)
        if (tid < 512) {
            int r = tid >> 4, w = tid & 15;
            int base = w * 32;
            int na = Q.nact[r];
            unsigned m = 0;
            for (int j = 0; j < na; ++j) {
                unsigned wpv = Q.ranges[r][j];
                int lo = max((int)(wpv & 0xffffu) - base, 0);
                int hi = min((int)(wpv >> 16) - base, 32);
                if (hi > lo) {
                    unsigned him = (hi == 32) ? 0xffffffffu : ((1u << hi) - 1u);
                    m |= him & ~((1u << lo) - 1u);
                }
            }
            Q.words[r][w] = m;
        }
        __syncthreads();

        // expand: warp r writes row h0+r (4 chunks of 128px, coalesced float4)
        {
            int r = wrp;
            float4* out = (float4*)(mask + ((long long)(b * HH + h0 + r)) * WW);
#pragma unroll
            for (int i = 0; i < 4; ++i) {
                unsigned word = Q.words[r][i * 4 + (lane >> 3)];
                unsigned nib = (word >> ((lane & 7) * 4)) & 0xfu;
                float4 o;
                o.x = (nib & 1u) ? 1.0f : 0.0f;
                o.y = (nib & 2u) ? 1.0f : 0.0f;
                o.z = (nib & 4u) ? 1.0f : 0.0f;
                o.w = (nib & 8u) ? 1.0f : 0.0f;
                out[i * 32 + lane] = o;
            }
        }
    }
}

// ---------------------------------------------------------------------------
extern "C" void kernel_launch(void* const* d_in, const int* in_sizes, int n_in,
                              void* d_out, int out_size) {
    const float* rois = (const float*)d_in[0];
    const float* probs = (const float*)d_in[1];
    const float* deltas = (const float*)d_in[2];
    const float* stdv = (const float*)d_in[3];
    float* det = (float*)d_out;                   // [B,100,6]
    float* mask = (float*)d_out + BB * MAXI * 6;  // [B,512,512]

    fused_all<<<GRID, 1024>>>(rois, probs, deltas, stdv, det, mask);
}